// round 15
// baseline (speedup 1.0000x reference)
#include <cuda_runtime.h>
#include <cuda_fp16.h>
#include <math.h>
#include <stdint.h>

#define NN    512
#define MEM   1024
#define KD    1024
#define TM3   3072
#define NINT  128
#define IBASE 384
#define NLVL  5

// ---------------- scratch (static device allocation, allowed) ----------------
__device__ float g_XI  [NN * TM3];          // x @ ioux_w^T (single slab)
__device__ float g_XFp [4 * NINT * MEM];    // x @ fx_w^T,  4 K-slices
__device__ float g_FHp [2 * 640 * MEM];     // h @ fh_w^T,  2 K-slices (padded rows)
__device__ float g_IOUp[4 * 64 * TM3];      // t_lvl @ iouh_w^T, 4 K-slices
__device__ float g_c   [NN * MEM];          // cell states
__device__ int   g_grp_nodes [NLVL][64];    // li, grouped by rel
__device__ int   g_grp_rel   [NLVL][49];    // rel id per active group
__device__ int   g_grp_startc[NLVL][50];    // prefix into grp_nodes
__device__ int   g_ngroups   [NLVL];

// fp16 operand copies
__device__ __half g_x16  [NN * KD];
__device__ __half g_ioxw16[TM3 * KD];
__device__ __half g_iohw16[TM3 * MEM];
__device__ __half g_fxw16[MEM * KD];
__device__ __half g_fhw16[MEM * MEM];
__device__ __half g_h16  [640 * MEM];       // padded rows (FH A-operand)
__device__ __half g_t16  [256 * MEM];       // padded rows (IOU A-operand)

__device__ __forceinline__ float sigm(float v) {
    return __fdividef(1.0f, 1.0f + __expf(-v));
}
__device__ __forceinline__ float ftanh(float v) {
    return 1.0f - __fdividef(2.0f, __expf(2.0f * v) + 1.0f);
}

// =================== async-copy / mma helpers ================================
__device__ __forceinline__ uint32_t s2u(const void* p) {
    uint32_t a;
    asm("{ .reg .u64 t; cvta.to.shared.u64 t, %1; cvt.u32.u64 %0, t; }"
        : "=r"(a) : "l"(p));
    return a;
}
__device__ __forceinline__ void cpa16(uint32_t dst, const void* src) {
    asm volatile("cp.async.cg.shared.global [%0], [%1], 16;"
                 :: "r"(dst), "l"(src) : "memory");
}
__device__ __forceinline__ void cpa_commit() {
    asm volatile("cp.async.commit_group;" ::: "memory");
}
__device__ __forceinline__ void cpa_wait2() {
    asm volatile("cp.async.wait_group 2;" ::: "memory");
}
__device__ __forceinline__ void cpa_wait1() {
    asm volatile("cp.async.wait_group 1;" ::: "memory");
}
__device__ __forceinline__ void cpa_wait0() {
    asm volatile("cp.async.wait_group 0;" ::: "memory");
}
__device__ __forceinline__ void mma16(float* c, const uint32_t* a, const uint32_t* b) {
    asm volatile(
        "mma.sync.aligned.m16n8k16.row.col.f32.f16.f16.f32 "
        "{%0,%1,%2,%3}, {%4,%5,%6,%7}, {%8,%9}, {%0,%1,%2,%3};"
        : "+f"(c[0]), "+f"(c[1]), "+f"(c[2]), "+f"(c[3])
        : "r"(a[0]), "r"(a[1]), "r"(a[2]), "r"(a[3]), "r"(b[0]), "r"(b[1]));
}

// ====== multi-problem fp16 mma.sync split-K GEMM, 3-stage cp.async ==========
struct GP {
    const __half* A; const __half* B; float* C;
    int N, Klen, slab, nx, ny, nz;
};
#define SMH     40
#define KSTRIDE 1024

template<int BM>
__global__ void __launch_bounds__(256) gemm2h(GP p0, GP p1)
{
    constexpr int WM = BM / 2;
    constexpr int MF = BM / 32;
    constexpr int ASZ = BM * SMH;
    constexpr int BSZ = 128 * SMH;
    constexpr int STG = ASZ + BSZ;

    extern __shared__ __half smh[];
    uint32_t uA[3], uB[3];
    #pragma unroll
    for (int s = 0; s < 3; s++) {
        uA[s] = s2u(smh + s * STG);
        uB[s] = s2u(smh + s * STG + ASZ);
    }

    int bid = blockIdx.x;
    GP p = p0;
    int t0 = p0.nx * p0.ny * p0.nz;
    if (bid >= t0) { bid -= t0; p = p1; }
    int bx = bid % p.nx;
    int by = (bid / p.nx) % p.ny;
    int bz = bid / (p.nx * p.ny);

    int tid = threadIdx.x;
    int lane = tid & 31, wid = tid >> 5;
    int wm = wid >> 2, wn = wid & 3;
    int gr = lane >> 2, qc = lane & 3;
    int m0 = by * BM, n0 = bx * 128;
    int koff = bz * p.Klen;

    const __half* Abase = p.A + (size_t)m0 * KSTRIDE + koff;
    const __half* Bbase = p.B + (size_t)n0 * KSTRIDE + koff;
    float* C = p.C + (size_t)bz * p.slab;
    const int NCH = p.Klen >> 5;

    float cacc[MF][4][4];
    #pragma unroll
    for (int i = 0; i < MF; i++)
        #pragma unroll
        for (int j = 0; j < 4; j++)
            #pragma unroll
            for (int e = 0; e < 4; e++) cacc[i][j][e] = 0.f;

    auto load_chunk = [&](int c, int buf) {
        const __half* Ap = Abase + c * 32;
        const __half* Bp = Bbase + c * 32;
        #pragma unroll
        for (int i = 0; i < BM / 64; i++) {
            int id = tid + i * 256;
            int row = id >> 2, c8 = (id & 3) << 3;
            cpa16(uA[buf] + (row * SMH + c8) * 2, Ap + (size_t)row * KSTRIDE + c8);
        }
        #pragma unroll
        for (int i = 0; i < 2; i++) {
            int id = tid + i * 256;
            int row = id >> 2, c8 = (id & 3) << 3;
            cpa16(uB[buf] + (row * SMH + c8) * 2, Bp + (size_t)row * KSTRIDE + c8);
        }
        cpa_commit();
    };

    load_chunk(0, 0);
    if (NCH > 1) load_chunk(1, 1);

    for (int c = 0; c < NCH; c++) {
        int buf = c % 3;
        if (c + 2 < NCH) load_chunk(c + 2, (c + 2) % 3);
        int left = NCH - 1 - c;
        if (left >= 2)      cpa_wait2();
        else if (left == 1) cpa_wait1();
        else                cpa_wait0();
        __syncthreads();

        const __half* As = smh + buf * STG;
        const __half* Bs = smh + buf * STG + ASZ;
        #pragma unroll
        for (int ks = 0; ks < 2; ks++) {
            int k0 = ks * 16 + 2 * qc;
            uint32_t b[4][2];
            #pragma unroll
            for (int ni = 0; ni < 4; ni++) {
                int nr = wn * 32 + ni * 8 + gr;
                b[ni][0] = *(const uint32_t*)&Bs[nr * SMH + k0];
                b[ni][1] = *(const uint32_t*)&Bs[nr * SMH + k0 + 8];
            }
            uint32_t a[MF][4];
            #pragma unroll
            for (int mi = 0; mi < MF; mi++) {
                int mr = wm * WM + mi * 16 + gr;
                a[mi][0] = *(const uint32_t*)&As[mr * SMH + k0];
                a[mi][1] = *(const uint32_t*)&As[(mr + 8) * SMH + k0];
                a[mi][2] = *(const uint32_t*)&As[mr * SMH + k0 + 8];
                a[mi][3] = *(const uint32_t*)&As[(mr + 8) * SMH + k0 + 8];
            }
            #pragma unroll
            for (int mi = 0; mi < MF; mi++)
                #pragma unroll
                for (int ni = 0; ni < 4; ni++)
                    mma16(cacc[mi][ni], a[mi], b[ni]);
        }
        __syncthreads();
    }

    #pragma unroll
    for (int mi = 0; mi < MF; mi++)
        #pragma unroll
        for (int ni = 0; ni < 4; ni++) {
            int row = m0 + wm * WM + mi * 16 + gr;
            int col = n0 + wn * 32 + ni * 8 + qc * 2;
            *(float2*)(C + (size_t)row * p.N + col) =
                make_float2(cacc[mi][ni][0], cacc[mi][ni][1]);
            *(float2*)(C + (size_t)(row + 8) * p.N + col) =
                make_float2(cacc[mi][ni][2], cacc[mi][ni][3]);
        }
}

// ------- merged fp32 -> fp16 conversion (5 segments) + prep (last block) -----
#define CV_E0 (NN * KD / 4)
#define CV_E1 (CV_E0 + TM3 * KD / 4)
#define CV_E2 (CV_E1 + TM3 * MEM / 4)
#define CV_E3 (CV_E2 + MEM * KD / 4)
#define CV_E4 (CV_E3 + MEM * MEM / 4)
#define CV_BLKS ((CV_E4 + 255) / 256)
__global__ void convh_k(const float* __restrict__ x,
                        const float* __restrict__ ioxw,
                        const float* __restrict__ iohw,
                        const float* __restrict__ fxw,
                        const float* __restrict__ fhw,
                        const int* __restrict__ rel_ids)
{
    if (blockIdx.x == CV_BLKS) {      // grouping block
        const int lvl_n0[NLVL]  = {384, 427, 491, 507, 511};
        const int lvl_cnt[NLVL] = { 43,  64,  16,   4,   1};
        int L = threadIdx.x;
        if (L >= NLVL) return;
        int cnt_r[49];
        for (int r = 0; r < 49; r++) cnt_r[r] = 0;
        int n0 = lvl_n0[L], cnt = lvl_cnt[L];
        for (int i = 0; i < cnt; i++) cnt_r[rel_ids[n0 + i]]++;
        int pos_of_rel[49];
        int ng = 0, acc = 0;
        for (int r = 0; r < 49; r++) {
            if (cnt_r[r] > 0) {
                g_grp_rel[L][ng] = r;
                g_grp_startc[L][ng] = acc;
                pos_of_rel[r] = acc;
                acc += cnt_r[r];
                ng++;
            }
        }
        g_grp_startc[L][ng] = acc;
        g_ngroups[L] = ng;
        for (int i = 0; i < cnt; i++) {
            int r = rel_ids[n0 + i];
            g_grp_nodes[L][pos_of_rel[r]++] = n0 + i - IBASE;
        }
        return;
    }
    int i = blockIdx.x * 256 + threadIdx.x;
    const float4* s; __half* d; int k;
    if      (i < CV_E0) { s = (const float4*)x;    d = g_x16;    k = i; }
    else if (i < CV_E1) { s = (const float4*)ioxw; d = g_ioxw16; k = i - CV_E0; }
    else if (i < CV_E2) { s = (const float4*)iohw; d = g_iohw16; k = i - CV_E1; }
    else if (i < CV_E3) { s = (const float4*)fxw;  d = g_fxw16;  k = i - CV_E2; }
    else if (i < CV_E4) { s = (const float4*)fhw;  d = g_fhw16;  k = i - CV_E3; }
    else return;
    float4 v = __ldcs(&s[k]);
    __half2 lo = __float22half2_rn(make_float2(v.x, v.y));
    __half2 hi = __float22half2_rn(make_float2(v.z, v.w));
    uint2 out = { *(uint32_t*)&lo, *(uint32_t*)&hi };
    ((uint2*)d)[k] = out;
}

// ---------------- leaves: nodes 0..383 (single XI slab) ----------------------
__global__ void leaf_k(float* __restrict__ h,
                       const float* __restrict__ ioux_b,
                       const float* __restrict__ iouh_b)
{
    int node = blockIdx.y;
    int j = blockIdx.x * 256 + threadIdx.x;
    const float* xi = g_XI + (size_t)node * TM3;
    float ig = sigm(__ldcs(xi + j) + ioux_b[j] + iouh_b[j]);
    float og = sigm(__ldcs(xi + MEM + j) + ioux_b[MEM + j] + iouh_b[MEM + j]);
    float ug = ftanh(__ldcs(xi + 2 * MEM + j)
                     + ioux_b[2 * MEM + j] + iouh_b[2 * MEM + j]);
    float cv = ig * ug;
    size_t idx = (size_t)node * MEM + j;
    g_c[idx] = cv;
    float hv = og * ftanh(cv);
    h[idx] = hv;
    g_h16[idx] = __float2half(hv);
}

// --- t = (child-sum of h) @ Wrel[rel]^T; W staged in SMEM via cp.async -------
// 256 threads, 8 rows/CTA (row = blockIdx.x*8 + warp), compact group index.
__global__ void __launch_bounds__(256) wrel3(const float* __restrict__ Wrel,
                                             const float* __restrict__ h,
                                             const int* __restrict__ child_idx,
                                             int lvl)
{
    int gi = blockIdx.y;
    if (gi >= g_ngroups[lvl]) return;
    int r  = g_grp_rel[lvl][gi];
    int s0 = g_grp_startc[lvl][gi];
    int g  = g_grp_startc[lvl][gi + 1] - s0;

    __shared__ float sW[8 * MEM];       // 32 KB
    __shared__ float sh[MEM];           //  4 KB
    int tid = threadIdx.x;
    int lane = tid & 31, wid = tid >> 5;
    int row0 = blockIdx.x * 8;          // global W row of warp 0
    bool ident = (r == 48);

    if (!ident) {
        // stage 8 W rows (8 x 4KB): 2048 float4 units, 256 units per row.
        const float* Wbase = Wrel + (size_t)r * (MEM * MEM) + (size_t)row0 * MEM;
        uint32_t uW = s2u(sW);
        #pragma unroll
        for (int i = 0; i < 8; i++) {
            int u = tid + i * 256;              // 0..2047
            int rr = u >> 8, c4 = (u & 255) << 2;
            cpa16(uW + (rr * MEM + c4) * 4, Wbase + (size_t)rr * MEM + c4);
        }
        cpa_commit();
    }

    for (int j = 0; j < g; j++) {
        int li = g_grp_nodes[lvl][s0 + j];
        int node = li + IBASE;
        const int* ci = child_idx + node * 4;
        int c0 = ci[0], c1 = ci[1], c2 = ci[2], c3 = ci[3];
        {   // fused child-sum (each thread one float4 of the 1024-vec)
            int i = tid;
            float4 s = make_float4(0.f, 0.f, 0.f, 0.f);
            if (c0 >= 0) { float4 v = ((const float4*)(h + (size_t)c0 * MEM))[i];
                           s.x += v.x; s.y += v.y; s.z += v.z; s.w += v.w; }
            if (c1 >= 0) { float4 v = ((const float4*)(h + (size_t)c1 * MEM))[i];
                           s.x += v.x; s.y += v.y; s.z += v.z; s.w += v.w; }
            if (c2 >= 0) { float4 v = ((const float4*)(h + (size_t)c2 * MEM))[i];
                           s.x += v.x; s.y += v.y; s.z += v.z; s.w += v.w; }
            if (c3 >= 0) { float4 v = ((const float4*)(h + (size_t)c3 * MEM))[i];
                           s.x += v.x; s.y += v.y; s.z += v.z; s.w += v.w; }
            ((float4*)sh)[i] = s;
        }
        if (j == 0 && !ident) cpa_wait0();
        __syncthreads();
        float s;
        if (ident) {
            s = sh[row0 + wid];
        } else {
            const float* Wr = sW + wid * MEM;
            s = 0.f;
            #pragma unroll
            for (int i = 0; i < 8; i++) {
                int k4 = (i * 32 + lane) * 4;
                float4 w = *(const float4*)(Wr + k4);
                s += w.x * sh[k4] + w.y * sh[k4 + 1]
                   + w.z * sh[k4 + 2] + w.w * sh[k4 + 3];
            }
            #pragma unroll
            for (int o = 16; o; o >>= 1) s += __shfl_xor_sync(0xffffffffu, s, o);
        }
        if (lane == 0) g_t16[(size_t)li * MEM + row0 + wid] = __float2half(s);
        if (j + 1 < g) __syncthreads();
    }
}

// --- fused: fc from children + gates -> h, c ---------------------------------
__global__ void cellfc_k(float* __restrict__ h,
                         const int* __restrict__ child_idx,
                         const float* __restrict__ ioux_b,
                         const float* __restrict__ iouh_b,
                         const float* __restrict__ fx_b,
                         const float* __restrict__ fh_b, int n0)
{
    int node = n0 + blockIdx.y;
    int li = node - IBASE;
    int j = blockIdx.x * 256 + threadIdx.x;
    const int* ci = child_idx + node * 4;

    float xf = 0.f;
    #pragma unroll
    for (int s = 0; s < 4; s++)
        xf += g_XFp[(size_t)s * (NINT * MEM) + (size_t)li * MEM + j];
    float base = xf + fx_b[j] + fh_b[j];

    float fc = 0.f;
    #pragma unroll
    for (int k = 0; k < 4; k++) {
        int c = ci[k];
        if (c >= 0) {
            float fh = g_FHp[(size_t)c * MEM + j]
                     + g_FHp[(size_t)(640 * MEM) + (size_t)c * MEM + j];
            fc += sigm(fh + base) * g_c[(size_t)c * MEM + j];
        }
    }

    float io0 = 0.f, io1 = 0.f, io2 = 0.f;
    #pragma unroll
    for (int s = 0; s < 4; s++) {
        const float* io = g_IOUp + (size_t)s * (64 * TM3) + (size_t)blockIdx.y * TM3;
        io0 += __ldcs(io + j); io1 += __ldcs(io + MEM + j); io2 += __ldcs(io + 2 * MEM + j);
    }
    const float* xi = g_XI + (size_t)node * TM3;

    float ig = sigm(io0 + __ldcs(xi + j) + ioux_b[j] + iouh_b[j]);
    float og = sigm(io1 + __ldcs(xi + MEM + j)
                    + ioux_b[MEM + j] + iouh_b[MEM + j]);
    float ug = ftanh(io2 + __ldcs(xi + 2 * MEM + j)
                     + ioux_b[2 * MEM + j] + iouh_b[2 * MEM + j]);
    float cv = ig * ug + fc;
    size_t idx = (size_t)node * MEM + j;
    g_c[idx] = cv;
    float hv = og * ftanh(cv);
    h[idx] = hv;
    g_h16[idx] = __float2half(hv);
}

// ------------------------------- launcher ------------------------------------
extern "C" void kernel_launch(void* const* d_in, const int* in_sizes, int n_in,
                              void* d_out, int out_size)
{
    const float* x       = (const float*)d_in[0];
    const float* Wrel    = (const float*)d_in[1];
    const float* ioux_w  = (const float*)d_in[2];
    const float* ioux_b  = (const float*)d_in[3];
    const float* iouh_w  = (const float*)d_in[4];
    const float* iouh_b  = (const float*)d_in[5];
    const float* fx_w    = (const float*)d_in[6];
    const float* fx_b    = (const float*)d_in[7];
    const float* fh_w    = (const float*)d_in[8];
    const float* fh_b    = (const float*)d_in[9];
    const int*   child_idx = (const int*)d_in[10];
    const int*   rel_ids   = (const int*)d_in[11];
    float* h = (float*)d_out;

    const int SM128H = 3 * (128 + 128) * SMH * 2;   // 61440 B
    const int SM64H  = 3 * (64 + 128) * SMH * 2;    // 46080 B
    cudaFuncSetAttribute(gemm2h<128>, cudaFuncAttributeMaxDynamicSharedMemorySize, SM128H);
    cudaFuncSetAttribute(gemm2h<64>,  cudaFuncAttributeMaxDynamicSharedMemorySize, SM64H);

    float *p_XI, *p_XFp, *p_FHp, *p_IOUp;
    __half *p_x16, *p_ioxw16, *p_iohw16, *p_fxw16, *p_fhw16, *p_h16, *p_t16;
    cudaGetSymbolAddress((void**)&p_XI,   g_XI);
    cudaGetSymbolAddress((void**)&p_XFp,  g_XFp);
    cudaGetSymbolAddress((void**)&p_FHp,  g_FHp);
    cudaGetSymbolAddress((void**)&p_IOUp, g_IOUp);
    cudaGetSymbolAddress((void**)&p_x16,    g_x16);
    cudaGetSymbolAddress((void**)&p_ioxw16, g_ioxw16);
    cudaGetSymbolAddress((void**)&p_iohw16, g_iohw16);
    cudaGetSymbolAddress((void**)&p_fxw16,  g_fxw16);
    cudaGetSymbolAddress((void**)&p_fhw16,  g_fhw16);
    cudaGetSymbolAddress((void**)&p_h16, g_h16);
    cudaGetSymbolAddress((void**)&p_t16, g_t16);

    // conversion + grouping in one launch
    convh_k<<<CV_BLKS + 1, 256>>>(x, ioux_w, iouh_w, fx_w, fh_w, rel_ids);

    // XI (512x3072, K=1024, z=1) + XF (128x1024, split-K x4), one launch
    GP pXI = { p_x16, p_ioxw16, p_XI, TM3, 1024, NN * TM3, 24, 4, 1 };
    GP pXF = { p_x16 + (size_t)IBASE * KD, p_fxw16, p_XFp, MEM, 256, NINT * MEM, 8, 1, 4 };
    gemm2h<128><<<24 * 4 * 1 + 8 * 1 * 4, 256, SM128H>>>(pXI, pXF);

    leaf_k<<<dim3(4, 384), 256>>>(h, ioux_b, iouh_b);

    const int lvl_n0[NLVL]   = {384, 427, 491, 507, 511};
    const int lvl_cnt[NLVL]  = { 43,  64,  16,   4,   1};
    const int lvl_ngmx[NLVL] = { 43,  49,  16,   4,   1};
    for (int L = 0; L < NLVL; L++) {
        int n0 = lvl_n0[L], cnt = lvl_cnt[L];

        wrel3<<<dim3(128, lvl_ngmx[L]), 256>>>(Wrel, h, child_idx, L);

        // IOU(L) (pad M to 64, split-K x4) + FH(previous level, split-K x2)
        GP pIOU = { p_t16 + (size_t)(n0 - IBASE) * MEM, p_iohw16, p_IOUp,
                    TM3, 256, 64 * TM3, 24, 1, 4 };
        GP pFH;
        if (L == 0)          // FH for all 384 leaves (6 x 64 rows)
            pFH = GP{ p_h16, p_fhw16, p_FHp, MEM, 512, 640 * MEM, 8, 6, 2 };
        else {               // FH for level L-1 nodes (64 padded rows)
            int np = lvl_n0[L - 1];
            pFH = GP{ p_h16 + (size_t)np * MEM, p_fhw16, p_FHp + (size_t)np * MEM,
                      MEM, 512, 640 * MEM, 8, 1, 2 };
        }
        int tot = pIOU.nx * pIOU.ny * pIOU.nz + pFH.nx * pFH.ny * pFH.nz;
        gemm2h<64><<<tot, 256, SM64H>>>(pIOU, pFH);

        cellfc_k<<<dim3(4, cnt), 256>>>(h, child_idx, ioux_b, iouh_b, fx_b, fh_b, n0);
    }
}

// round 16
// speedup vs baseline: 1.1171x; 1.1171x over previous
#include <cuda_runtime.h>
#include <cuda_fp16.h>
#include <math.h>
#include <stdint.h>

#define NN    512
#define MEM   1024
#define KD    1024
#define TM3   3072
#define NINT  128
#define IBASE 384
#define NLVL  5

// ---------------- scratch (static device allocation, allowed) ----------------
__device__ float g_XI  [NN * TM3];          // x @ ioux_w^T (single slab)
__device__ float g_XFp [4 * NINT * MEM];    // x @ fx_w^T,  4 K-slices
__device__ float g_FHp [2 * 640 * MEM];     // h @ fh_w^T,  2 K-slices (padded rows)
__device__ float g_IOUp[4 * 64 * TM3];      // t_lvl @ iouh_w^T, 4 K-slices
__device__ float g_c   [NN * MEM];          // cell states
__device__ int   g_grp_nodes [NLVL][64];    // li, grouped by rel
__device__ int   g_grp_rel   [NLVL][49];    // rel id per active group
__device__ int   g_grp_startc[NLVL][50];    // prefix into grp_nodes
__device__ int   g_ngroups   [NLVL];

// fp16 operand copies
__device__ __half g_x16  [NN * KD];
__device__ __half g_ioxw16[TM3 * KD];
__device__ __half g_iohw16[TM3 * MEM];
__device__ __half g_fxw16[MEM * KD];
__device__ __half g_fhw16[MEM * MEM];
__device__ __half g_h16  [640 * MEM];       // padded rows (FH A-operand)
__device__ __half g_t16  [256 * MEM];       // padded rows (IOU A-operand)

__device__ __forceinline__ float sigm(float v) {
    return __fdividef(1.0f, 1.0f + __expf(-v));
}
__device__ __forceinline__ float ftanh(float v) {
    return 1.0f - __fdividef(2.0f, __expf(2.0f * v) + 1.0f);
}

// =================== async-copy / mma helpers ================================
__device__ __forceinline__ uint32_t s2u(const void* p) {
    uint32_t a;
    asm("{ .reg .u64 t; cvta.to.shared.u64 t, %1; cvt.u32.u64 %0, t; }"
        : "=r"(a) : "l"(p));
    return a;
}
__device__ __forceinline__ void cpa16(uint32_t dst, const void* src) {
    asm volatile("cp.async.cg.shared.global [%0], [%1], 16;"
                 :: "r"(dst), "l"(src) : "memory");
}
__device__ __forceinline__ void cpa_commit() {
    asm volatile("cp.async.commit_group;" ::: "memory");
}
__device__ __forceinline__ void cpa_wait2() {
    asm volatile("cp.async.wait_group 2;" ::: "memory");
}
__device__ __forceinline__ void cpa_wait1() {
    asm volatile("cp.async.wait_group 1;" ::: "memory");
}
__device__ __forceinline__ void cpa_wait0() {
    asm volatile("cp.async.wait_group 0;" ::: "memory");
}
__device__ __forceinline__ void mma16(float* c, const uint32_t* a, const uint32_t* b) {
    asm volatile(
        "mma.sync.aligned.m16n8k16.row.col.f32.f16.f16.f32 "
        "{%0,%1,%2,%3}, {%4,%5,%6,%7}, {%8,%9}, {%0,%1,%2,%3};"
        : "+f"(c[0]), "+f"(c[1]), "+f"(c[2]), "+f"(c[3])
        : "r"(a[0]), "r"(a[1]), "r"(a[2]), "r"(a[3]), "r"(b[0]), "r"(b[1]));
}

// ====== multi-problem fp16 mma.sync split-K GEMM, 3-stage cp.async ==========
struct GP {
    const __half* A; const __half* B; float* C;
    int N, Klen, slab, nx, ny, nz;
};
#define SMH     40
#define KSTRIDE 1024

template<int BM>
__global__ void __launch_bounds__(256) gemm2h(GP p0, GP p1)
{
    constexpr int WM = BM / 2;
    constexpr int MF = BM / 32;
    constexpr int ASZ = BM * SMH;
    constexpr int BSZ = 128 * SMH;
    constexpr int STG = ASZ + BSZ;

    extern __shared__ __half smh[];
    uint32_t uA[3], uB[3];
    #pragma unroll
    for (int s = 0; s < 3; s++) {
        uA[s] = s2u(smh + s * STG);
        uB[s] = s2u(smh + s * STG + ASZ);
    }

    int bid = blockIdx.x;
    GP p = p0;
    int t0 = p0.nx * p0.ny * p0.nz;
    if (bid >= t0) { bid -= t0; p = p1; }
    int bx = bid % p.nx;
    int by = (bid / p.nx) % p.ny;
    int bz = bid / (p.nx * p.ny);

    int tid = threadIdx.x;
    int lane = tid & 31, wid = tid >> 5;
    int wm = wid >> 2, wn = wid & 3;
    int gr = lane >> 2, qc = lane & 3;
    int m0 = by * BM, n0 = bx * 128;
    int koff = bz * p.Klen;

    const __half* Abase = p.A + (size_t)m0 * KSTRIDE + koff;
    const __half* Bbase = p.B + (size_t)n0 * KSTRIDE + koff;
    float* C = p.C + (size_t)bz * p.slab;
    const int NCH = p.Klen >> 5;

    float cacc[MF][4][4];
    #pragma unroll
    for (int i = 0; i < MF; i++)
        #pragma unroll
        for (int j = 0; j < 4; j++)
            #pragma unroll
            for (int e = 0; e < 4; e++) cacc[i][j][e] = 0.f;

    auto load_chunk = [&](int c, int buf) {
        const __half* Ap = Abase + c * 32;
        const __half* Bp = Bbase + c * 32;
        #pragma unroll
        for (int i = 0; i < BM / 64; i++) {
            int id = tid + i * 256;
            int row = id >> 2, c8 = (id & 3) << 3;
            cpa16(uA[buf] + (row * SMH + c8) * 2, Ap + (size_t)row * KSTRIDE + c8);
        }
        #pragma unroll
        for (int i = 0; i < 2; i++) {
            int id = tid + i * 256;
            int row = id >> 2, c8 = (id & 3) << 3;
            cpa16(uB[buf] + (row * SMH + c8) * 2, Bp + (size_t)row * KSTRIDE + c8);
        }
        cpa_commit();
    };

    load_chunk(0, 0);
    if (NCH > 1) load_chunk(1, 1);

    for (int c = 0; c < NCH; c++) {
        int buf = c % 3;
        if (c + 2 < NCH) load_chunk(c + 2, (c + 2) % 3);
        int left = NCH - 1 - c;
        if (left >= 2)      cpa_wait2();
        else if (left == 1) cpa_wait1();
        else                cpa_wait0();
        __syncthreads();

        const __half* As = smh + buf * STG;
        const __half* Bs = smh + buf * STG + ASZ;
        #pragma unroll
        for (int ks = 0; ks < 2; ks++) {
            int k0 = ks * 16 + 2 * qc;
            uint32_t b[4][2];
            #pragma unroll
            for (int ni = 0; ni < 4; ni++) {
                int nr = wn * 32 + ni * 8 + gr;
                b[ni][0] = *(const uint32_t*)&Bs[nr * SMH + k0];
                b[ni][1] = *(const uint32_t*)&Bs[nr * SMH + k0 + 8];
            }
            uint32_t a[MF][4];
            #pragma unroll
            for (int mi = 0; mi < MF; mi++) {
                int mr = wm * WM + mi * 16 + gr;
                a[mi][0] = *(const uint32_t*)&As[mr * SMH + k0];
                a[mi][1] = *(const uint32_t*)&As[(mr + 8) * SMH + k0];
                a[mi][2] = *(const uint32_t*)&As[mr * SMH + k0 + 8];
                a[mi][3] = *(const uint32_t*)&As[(mr + 8) * SMH + k0 + 8];
            }
            #pragma unroll
            for (int mi = 0; mi < MF; mi++)
                #pragma unroll
                for (int ni = 0; ni < 4; ni++)
                    mma16(cacc[mi][ni], a[mi], b[ni]);
        }
        __syncthreads();
    }

    #pragma unroll
    for (int mi = 0; mi < MF; mi++)
        #pragma unroll
        for (int ni = 0; ni < 4; ni++) {
            int row = m0 + wm * WM + mi * 16 + gr;
            int col = n0 + wn * 32 + ni * 8 + qc * 2;
            *(float2*)(C + (size_t)row * p.N + col) =
                make_float2(cacc[mi][ni][0], cacc[mi][ni][1]);
            *(float2*)(C + (size_t)(row + 8) * p.N + col) =
                make_float2(cacc[mi][ni][2], cacc[mi][ni][3]);
        }
}

// ------- merged fp32 -> fp16 conversion (5 segments) + prep (last block) -----
#define CV_E0 (NN * KD / 4)
#define CV_E1 (CV_E0 + TM3 * KD / 4)
#define CV_E2 (CV_E1 + TM3 * MEM / 4)
#define CV_E3 (CV_E2 + MEM * KD / 4)
#define CV_E4 (CV_E3 + MEM * MEM / 4)
#define CV_BLKS ((CV_E4 + 255) / 256)
__global__ void convh_k(const float* __restrict__ x,
                        const float* __restrict__ ioxw,
                        const float* __restrict__ iohw,
                        const float* __restrict__ fxw,
                        const float* __restrict__ fhw,
                        const int* __restrict__ rel_ids)
{
    if (blockIdx.x == CV_BLKS) {      // grouping block
        const int lvl_n0[NLVL]  = {384, 427, 491, 507, 511};
        const int lvl_cnt[NLVL] = { 43,  64,  16,   4,   1};
        int L = threadIdx.x;
        if (L >= NLVL) return;
        int cnt_r[49];
        for (int r = 0; r < 49; r++) cnt_r[r] = 0;
        int n0 = lvl_n0[L], cnt = lvl_cnt[L];
        for (int i = 0; i < cnt; i++) cnt_r[rel_ids[n0 + i]]++;
        int pos_of_rel[49];
        int ng = 0, acc = 0;
        for (int r = 0; r < 49; r++) {
            if (cnt_r[r] > 0) {
                g_grp_rel[L][ng] = r;
                g_grp_startc[L][ng] = acc;
                pos_of_rel[r] = acc;
                acc += cnt_r[r];
                ng++;
            }
        }
        g_grp_startc[L][ng] = acc;
        g_ngroups[L] = ng;
        for (int i = 0; i < cnt; i++) {
            int r = rel_ids[n0 + i];
            g_grp_nodes[L][pos_of_rel[r]++] = n0 + i - IBASE;
        }
        return;
    }
    int i = blockIdx.x * 256 + threadIdx.x;
    const float4* s; __half* d; int k;
    if      (i < CV_E0) { s = (const float4*)x;    d = g_x16;    k = i; }
    else if (i < CV_E1) { s = (const float4*)ioxw; d = g_ioxw16; k = i - CV_E0; }
    else if (i < CV_E2) { s = (const float4*)iohw; d = g_iohw16; k = i - CV_E1; }
    else if (i < CV_E3) { s = (const float4*)fxw;  d = g_fxw16;  k = i - CV_E2; }
    else if (i < CV_E4) { s = (const float4*)fhw;  d = g_fhw16;  k = i - CV_E3; }
    else return;
    float4 v = __ldcs(&s[k]);
    __half2 lo = __float22half2_rn(make_float2(v.x, v.y));
    __half2 hi = __float22half2_rn(make_float2(v.z, v.w));
    uint2 out = { *(uint32_t*)&lo, *(uint32_t*)&hi };
    ((uint2*)d)[k] = out;
}

// ---------------- leaves: nodes 0..383 (single XI slab) ----------------------
__global__ void leaf_k(float* __restrict__ h,
                       const float* __restrict__ ioux_b,
                       const float* __restrict__ iouh_b)
{
    int node = blockIdx.y;
    int j = blockIdx.x * 256 + threadIdx.x;
    const float* xi = g_XI + (size_t)node * TM3;
    float ig = sigm(__ldcs(xi + j) + ioux_b[j] + iouh_b[j]);
    float og = sigm(__ldcs(xi + MEM + j) + ioux_b[MEM + j] + iouh_b[MEM + j]);
    float ug = ftanh(__ldcs(xi + 2 * MEM + j)
                     + ioux_b[2 * MEM + j] + iouh_b[2 * MEM + j]);
    float cv = ig * ug;
    size_t idx = (size_t)node * MEM + j;
    g_c[idx] = cv;
    float hv = og * ftanh(cv);
    h[idx] = hv;
    g_h16[idx] = __float2half(hv);
}

// --- t = (child-sum of h) @ Wrel[rel]^T; champion register-W version,
//     compact group index (grid.y = active groups, early exit) ---------------
__global__ void __launch_bounds__(256) wrel_grp(const float* __restrict__ Wrel,
                                                const float* __restrict__ h,
                                                const int* __restrict__ child_idx,
                                                int lvl)
{
    int gi = blockIdx.y;
    if (gi >= g_ngroups[lvl]) return;
    int r  = g_grp_rel[lvl][gi];
    int s0 = g_grp_startc[lvl][gi];
    int g  = g_grp_startc[lvl][gi + 1] - s0;

    __shared__ float sh[MEM];
    int lane = threadIdx.x & 31, wid = threadIdx.x >> 5;
    int row = blockIdx.x * 8 + wid;
    bool ident = (r == 48);
    float4 w[8];
    if (!ident) {
        const float* W = Wrel + (size_t)r * (MEM * MEM) + (size_t)row * MEM;
        #pragma unroll
        for (int i = 0; i < 8; i++)
            w[i] = __ldcs((const float4*)(W + (i * 32 + lane) * 4));
    }
    for (int j = 0; j < g; j++) {
        int li = g_grp_nodes[lvl][s0 + j];
        int node = li + IBASE;
        const int* ci = child_idx + node * 4;
        int c0 = ci[0], c1 = ci[1], c2 = ci[2], c3 = ci[3];
        {
            int i = threadIdx.x;
            float4 s = make_float4(0.f, 0.f, 0.f, 0.f);
            if (c0 >= 0) { float4 v = ((const float4*)(h + (size_t)c0 * MEM))[i];
                           s.x += v.x; s.y += v.y; s.z += v.z; s.w += v.w; }
            if (c1 >= 0) { float4 v = ((const float4*)(h + (size_t)c1 * MEM))[i];
                           s.x += v.x; s.y += v.y; s.z += v.z; s.w += v.w; }
            if (c2 >= 0) { float4 v = ((const float4*)(h + (size_t)c2 * MEM))[i];
                           s.x += v.x; s.y += v.y; s.z += v.z; s.w += v.w; }
            if (c3 >= 0) { float4 v = ((const float4*)(h + (size_t)c3 * MEM))[i];
                           s.x += v.x; s.y += v.y; s.z += v.z; s.w += v.w; }
            ((float4*)sh)[i] = s;
        }
        __syncthreads();
        float s;
        if (ident) {
            s = sh[row];
        } else {
            s = 0.f;
            #pragma unroll
            for (int i = 0; i < 8; i++) {
                int k4 = (i * 32 + lane) * 4;
                s += w[i].x * sh[k4] + w[i].y * sh[k4 + 1]
                   + w[i].z * sh[k4 + 2] + w[i].w * sh[k4 + 3];
            }
            #pragma unroll
            for (int o = 16; o; o >>= 1) s += __shfl_xor_sync(0xffffffffu, s, o);
        }
        if (lane == 0) g_t16[(size_t)li * MEM + row] = __float2half(s);
        if (j + 1 < g) __syncthreads();
    }
}

// --- fused: fc from children + gates -> h, c ---------------------------------
__global__ void cellfc_k(float* __restrict__ h,
                         const int* __restrict__ child_idx,
                         const float* __restrict__ ioux_b,
                         const float* __restrict__ iouh_b,
                         const float* __restrict__ fx_b,
                         const float* __restrict__ fh_b, int n0)
{
    int node = n0 + blockIdx.y;
    int li = node - IBASE;
    int j = blockIdx.x * 256 + threadIdx.x;
    const int* ci = child_idx + node * 4;

    float xf = 0.f;
    #pragma unroll
    for (int s = 0; s < 4; s++)
        xf += g_XFp[(size_t)s * (NINT * MEM) + (size_t)li * MEM + j];
    float base = xf + fx_b[j] + fh_b[j];

    float fc = 0.f;
    #pragma unroll
    for (int k = 0; k < 4; k++) {
        int c = ci[k];
        if (c >= 0) {
            float fh = g_FHp[(size_t)c * MEM + j]
                     + g_FHp[(size_t)(640 * MEM) + (size_t)c * MEM + j];
            fc += sigm(fh + base) * g_c[(size_t)c * MEM + j];
        }
    }

    float io0 = 0.f, io1 = 0.f, io2 = 0.f;
    #pragma unroll
    for (int s = 0; s < 4; s++) {
        const float* io = g_IOUp + (size_t)s * (64 * TM3) + (size_t)blockIdx.y * TM3;
        io0 += __ldcs(io + j); io1 += __ldcs(io + MEM + j); io2 += __ldcs(io + 2 * MEM + j);
    }
    const float* xi = g_XI + (size_t)node * TM3;

    float ig = sigm(io0 + __ldcs(xi + j) + ioux_b[j] + iouh_b[j]);
    float og = sigm(io1 + __ldcs(xi + MEM + j)
                    + ioux_b[MEM + j] + iouh_b[MEM + j]);
    float ug = ftanh(io2 + __ldcs(xi + 2 * MEM + j)
                     + ioux_b[2 * MEM + j] + iouh_b[2 * MEM + j]);
    float cv = ig * ug + fc;
    size_t idx = (size_t)node * MEM + j;
    g_c[idx] = cv;
    float hv = og * ftanh(cv);
    h[idx] = hv;
    g_h16[idx] = __float2half(hv);
}

// ------------------------------- launcher ------------------------------------
extern "C" void kernel_launch(void* const* d_in, const int* in_sizes, int n_in,
                              void* d_out, int out_size)
{
    const float* x       = (const float*)d_in[0];
    const float* Wrel    = (const float*)d_in[1];
    const float* ioux_w  = (const float*)d_in[2];
    const float* ioux_b  = (const float*)d_in[3];
    const float* iouh_w  = (const float*)d_in[4];
    const float* iouh_b  = (const float*)d_in[5];
    const float* fx_w    = (const float*)d_in[6];
    const float* fx_b    = (const float*)d_in[7];
    const float* fh_w    = (const float*)d_in[8];
    const float* fh_b    = (const float*)d_in[9];
    const int*   child_idx = (const int*)d_in[10];
    const int*   rel_ids   = (const int*)d_in[11];
    float* h = (float*)d_out;

    const int SM128H = 3 * (128 + 128) * SMH * 2;   // 61440 B
    const int SM64H  = 3 * (64 + 128) * SMH * 2;    // 46080 B
    cudaFuncSetAttribute(gemm2h<128>, cudaFuncAttributeMaxDynamicSharedMemorySize, SM128H);
    cudaFuncSetAttribute(gemm2h<64>,  cudaFuncAttributeMaxDynamicSharedMemorySize, SM64H);

    float *p_XI, *p_XFp, *p_FHp, *p_IOUp;
    __half *p_x16, *p_ioxw16, *p_iohw16, *p_fxw16, *p_fhw16, *p_h16, *p_t16;
    cudaGetSymbolAddress((void**)&p_XI,   g_XI);
    cudaGetSymbolAddress((void**)&p_XFp,  g_XFp);
    cudaGetSymbolAddress((void**)&p_FHp,  g_FHp);
    cudaGetSymbolAddress((void**)&p_IOUp, g_IOUp);
    cudaGetSymbolAddress((void**)&p_x16,    g_x16);
    cudaGetSymbolAddress((void**)&p_ioxw16, g_ioxw16);
    cudaGetSymbolAddress((void**)&p_iohw16, g_iohw16);
    cudaGetSymbolAddress((void**)&p_fxw16,  g_fxw16);
    cudaGetSymbolAddress((void**)&p_fhw16,  g_fhw16);
    cudaGetSymbolAddress((void**)&p_h16, g_h16);
    cudaGetSymbolAddress((void**)&p_t16, g_t16);

    // conversion + grouping in one launch
    convh_k<<<CV_BLKS + 1, 256>>>(x, ioux_w, iouh_w, fx_w, fh_w, rel_ids);

    // XI (512x3072, K=1024, z=1) + XF (128x1024, split-K x4), one launch
    GP pXI = { p_x16, p_ioxw16, p_XI, TM3, 1024, NN * TM3, 24, 4, 1 };
    GP pXF = { p_x16 + (size_t)IBASE * KD, p_fxw16, p_XFp, MEM, 256, NINT * MEM, 8, 1, 4 };
    gemm2h<128><<<24 * 4 * 1 + 8 * 1 * 4, 256, SM128H>>>(pXI, pXF);

    leaf_k<<<dim3(4, 384), 256>>>(h, ioux_b, iouh_b);

    const int lvl_n0[NLVL]   = {384, 427, 491, 507, 511};
    const int lvl_cnt[NLVL]  = { 43,  64,  16,   4,   1};
    const int lvl_ngmx[NLVL] = { 43,  49,  16,   4,   1};
    for (int L = 0; L < NLVL; L++) {
        int n0 = lvl_n0[L], cnt = lvl_cnt[L];

        wrel_grp<<<dim3(128, lvl_ngmx[L]), 256>>>(Wrel, h, child_idx, L);

        // IOU(L) (pad M to 64, split-K x4) + FH(previous level, split-K x2)
        GP pIOU = { p_t16 + (size_t)(n0 - IBASE) * MEM, p_iohw16, p_IOUp,
                    TM3, 256, 64 * TM3, 24, 1, 4 };
        GP pFH;
        if (L == 0)          // FH for all 384 leaves (6 x 64 rows)
            pFH = GP{ p_h16, p_fhw16, p_FHp, MEM, 512, 640 * MEM, 8, 6, 2 };
        else {               // FH for level L-1 nodes (64 padded rows)
            int np = lvl_n0[L - 1];
            pFH = GP{ p_h16 + (size_t)np * MEM, p_fhw16, p_FHp + (size_t)np * MEM,
                      MEM, 512, 640 * MEM, 8, 1, 2 };
        }
        int tot = pIOU.nx * pIOU.ny * pIOU.nz + pFH.nx * pFH.ny * pFH.nz;
        gemm2h<64><<<tot, 256, SM64H>>>(pIOU, pFH);

        cellfc_k<<<dim3(4, cnt), 256>>>(h, child_idx, ioux_b, iouh_b, fx_b, fh_b, n0);
    }
}

// round 17
// speedup vs baseline: 1.1313x; 1.0126x over previous
#include <cuda_runtime.h>
#include <cuda_fp16.h>
#include <math.h>
#include <stdint.h>

#define NN    512
#define MEM   1024
#define KD    1024
#define TM3   3072
#define NINT  128
#define IBASE 384
#define NLVL  5

// ---------------- scratch (static device allocation, allowed) ----------------
__device__ float g_XI  [NN * TM3];          // x @ ioux_w^T (single slab)
__device__ float g_XFp [4 * NINT * MEM];    // x @ fx_w^T,  4 K-slices
__device__ float g_FHp [2 * 640 * MEM];     // h @ fh_w^T,  2 K-slices (padded rows)
__device__ float g_IOUp[4 * 128 * TM3];     // t_phase @ iouh_w^T, 4 K-slices (128-row slabs)
__device__ float g_c   [NN * MEM];          // cell states
__device__ int   g_grp_nodes [NLVL][96];    // li, grouped by rel (phase max 96 nodes)
__device__ int   g_grp_rel   [NLVL][49];    // rel id per active group
__device__ int   g_grp_startc[NLVL][50];    // prefix into grp_nodes
__device__ int   g_ngroups   [NLVL];

// fp16 operand copies
__device__ __half g_x16  [NN * KD];
__device__ __half g_ioxw16[TM3 * KD];
__device__ __half g_iohw16[TM3 * MEM];
__device__ __half g_fxw16[MEM * KD];
__device__ __half g_fhw16[MEM * MEM];
__device__ __half g_h16  [640 * MEM];       // padded rows (FH A-operand)
__device__ __half g_t16  [256 * MEM];       // padded rows (IOU A-operand)

__device__ __forceinline__ float sigm(float v) {
    return __fdividef(1.0f, 1.0f + __expf(-v));
}
__device__ __forceinline__ float ftanh(float v) {
    return 1.0f - __fdividef(2.0f, __expf(2.0f * v) + 1.0f);
}

// =================== async-copy / mma helpers ================================
__device__ __forceinline__ uint32_t s2u(const void* p) {
    uint32_t a;
    asm("{ .reg .u64 t; cvta.to.shared.u64 t, %1; cvt.u32.u64 %0, t; }"
        : "=r"(a) : "l"(p));
    return a;
}
__device__ __forceinline__ void cpa16(uint32_t dst, const void* src) {
    asm volatile("cp.async.cg.shared.global [%0], [%1], 16;"
                 :: "r"(dst), "l"(src) : "memory");
}
__device__ __forceinline__ void cpa_commit() {
    asm volatile("cp.async.commit_group;" ::: "memory");
}
__device__ __forceinline__ void cpa_wait2() {
    asm volatile("cp.async.wait_group 2;" ::: "memory");
}
__device__ __forceinline__ void cpa_wait1() {
    asm volatile("cp.async.wait_group 1;" ::: "memory");
}
__device__ __forceinline__ void cpa_wait0() {
    asm volatile("cp.async.wait_group 0;" ::: "memory");
}
__device__ __forceinline__ void mma16(float* c, const uint32_t* a, const uint32_t* b) {
    asm volatile(
        "mma.sync.aligned.m16n8k16.row.col.f32.f16.f16.f32 "
        "{%0,%1,%2,%3}, {%4,%5,%6,%7}, {%8,%9}, {%0,%1,%2,%3};"
        : "+f"(c[0]), "+f"(c[1]), "+f"(c[2]), "+f"(c[3])
        : "r"(a[0]), "r"(a[1]), "r"(a[2]), "r"(a[3]), "r"(b[0]), "r"(b[1]));
}

// ====== multi-problem fp16 mma.sync split-K GEMM, 3-stage cp.async ==========
struct GP {
    const __half* A; const __half* B; float* C;
    int N, Klen, slab, nx, ny, nz;
};
#define SMH     40
#define KSTRIDE 1024

template<int BM>
__global__ void __launch_bounds__(256) gemm2h(GP p0, GP p1)
{
    constexpr int WM = BM / 2;
    constexpr int MF = BM / 32;
    constexpr int ASZ = BM * SMH;
    constexpr int BSZ = 128 * SMH;
    constexpr int STG = ASZ + BSZ;

    extern __shared__ __half smh[];
    uint32_t uA[3], uB[3];
    #pragma unroll
    for (int s = 0; s < 3; s++) {
        uA[s] = s2u(smh + s * STG);
        uB[s] = s2u(smh + s * STG + ASZ);
    }

    int bid = blockIdx.x;
    GP p = p0;
    int t0 = p0.nx * p0.ny * p0.nz;
    if (bid >= t0) { bid -= t0; p = p1; }
    int bx = bid % p.nx;
    int by = (bid / p.nx) % p.ny;
    int bz = bid / (p.nx * p.ny);

    int tid = threadIdx.x;
    int lane = tid & 31, wid = tid >> 5;
    int wm = wid >> 2, wn = wid & 3;
    int gr = lane >> 2, qc = lane & 3;
    int m0 = by * BM, n0 = bx * 128;
    int koff = bz * p.Klen;

    const __half* Abase = p.A + (size_t)m0 * KSTRIDE + koff;
    const __half* Bbase = p.B + (size_t)n0 * KSTRIDE + koff;
    float* C = p.C + (size_t)bz * p.slab;
    const int NCH = p.Klen >> 5;

    float cacc[MF][4][4];
    #pragma unroll
    for (int i = 0; i < MF; i++)
        #pragma unroll
        for (int j = 0; j < 4; j++)
            #pragma unroll
            for (int e = 0; e < 4; e++) cacc[i][j][e] = 0.f;

    auto load_chunk = [&](int c, int buf) {
        const __half* Ap = Abase + c * 32;
        const __half* Bp = Bbase + c * 32;
        #pragma unroll
        for (int i = 0; i < BM / 64; i++) {
            int id = tid + i * 256;
            int row = id >> 2, c8 = (id & 3) << 3;
            cpa16(uA[buf] + (row * SMH + c8) * 2, Ap + (size_t)row * KSTRIDE + c8);
        }
        #pragma unroll
        for (int i = 0; i < 2; i++) {
            int id = tid + i * 256;
            int row = id >> 2, c8 = (id & 3) << 3;
            cpa16(uB[buf] + (row * SMH + c8) * 2, Bp + (size_t)row * KSTRIDE + c8);
        }
        cpa_commit();
    };

    load_chunk(0, 0);
    if (NCH > 1) load_chunk(1, 1);

    for (int c = 0; c < NCH; c++) {
        int buf = c % 3;
        if (c + 2 < NCH) load_chunk(c + 2, (c + 2) % 3);
        int left = NCH - 1 - c;
        if (left >= 2)      cpa_wait2();
        else if (left == 1) cpa_wait1();
        else                cpa_wait0();
        __syncthreads();

        const __half* As = smh + buf * STG;
        const __half* Bs = smh + buf * STG + ASZ;
        #pragma unroll
        for (int ks = 0; ks < 2; ks++) {
            int k0 = ks * 16 + 2 * qc;
            uint32_t b[4][2];
            #pragma unroll
            for (int ni = 0; ni < 4; ni++) {
                int nr = wn * 32 + ni * 8 + gr;
                b[ni][0] = *(const uint32_t*)&Bs[nr * SMH + k0];
                b[ni][1] = *(const uint32_t*)&Bs[nr * SMH + k0 + 8];
            }
            uint32_t a[MF][4];
            #pragma unroll
            for (int mi = 0; mi < MF; mi++) {
                int mr = wm * WM + mi * 16 + gr;
                a[mi][0] = *(const uint32_t*)&As[mr * SMH + k0];
                a[mi][1] = *(const uint32_t*)&As[(mr + 8) * SMH + k0];
                a[mi][2] = *(const uint32_t*)&As[mr * SMH + k0 + 8];
                a[mi][3] = *(const uint32_t*)&As[(mr + 8) * SMH + k0 + 8];
            }
            #pragma unroll
            for (int mi = 0; mi < MF; mi++)
                #pragma unroll
                for (int ni = 0; ni < 4; ni++)
                    mma16(cacc[mi][ni], a[mi], b[ni]);
        }
        __syncthreads();
    }

    #pragma unroll
    for (int mi = 0; mi < MF; mi++)
        #pragma unroll
        for (int ni = 0; ni < 4; ni++) {
            int row = m0 + wm * WM + mi * 16 + gr;
            int col = n0 + wn * 32 + ni * 8 + qc * 2;
            *(float2*)(C + (size_t)row * p.N + col) =
                make_float2(cacc[mi][ni][0], cacc[mi][ni][1]);
            *(float2*)(C + (size_t)(row + 8) * p.N + col) =
                make_float2(cacc[mi][ni][2], cacc[mi][ni][3]);
        }
}

// ------- merged fp32 -> fp16 conversion (5 segments) + prep (last block) -----
// Dependency-minimal phases: P0=384..479(96) P1=480..503(24) P2=504..509(6)
// P3=510(1) P4=511(1)  [heap j>=32 has only leaf children]
#define CV_E0 (NN * KD / 4)
#define CV_E1 (CV_E0 + TM3 * KD / 4)
#define CV_E2 (CV_E1 + TM3 * MEM / 4)
#define CV_E3 (CV_E2 + MEM * KD / 4)
#define CV_E4 (CV_E3 + MEM * MEM / 4)
#define CV_BLKS ((CV_E4 + 255) / 256)
__global__ void convh_k(const float* __restrict__ x,
                        const float* __restrict__ ioxw,
                        const float* __restrict__ iohw,
                        const float* __restrict__ fxw,
                        const float* __restrict__ fhw,
                        const int* __restrict__ rel_ids)
{
    if (blockIdx.x == CV_BLKS) {      // grouping block
        const int lvl_n0[NLVL]  = {384, 480, 504, 510, 511};
        const int lvl_cnt[NLVL] = { 96,  24,   6,   1,   1};
        int L = threadIdx.x;
        if (L >= NLVL) return;
        int cnt_r[49];
        for (int r = 0; r < 49; r++) cnt_r[r] = 0;
        int n0 = lvl_n0[L], cnt = lvl_cnt[L];
        for (int i = 0; i < cnt; i++) cnt_r[rel_ids[n0 + i]]++;
        int pos_of_rel[49];
        int ng = 0, acc = 0;
        for (int r = 0; r < 49; r++) {
            if (cnt_r[r] > 0) {
                g_grp_rel[L][ng] = r;
                g_grp_startc[L][ng] = acc;
                pos_of_rel[r] = acc;
                acc += cnt_r[r];
                ng++;
            }
        }
        g_grp_startc[L][ng] = acc;
        g_ngroups[L] = ng;
        for (int i = 0; i < cnt; i++) {
            int r = rel_ids[n0 + i];
            g_grp_nodes[L][pos_of_rel[r]++] = n0 + i - IBASE;
        }
        return;
    }
    int i = blockIdx.x * 256 + threadIdx.x;
    const float4* s; __half* d; int k;
    if      (i < CV_E0) { s = (const float4*)x;    d = g_x16;    k = i; }
    else if (i < CV_E1) { s = (const float4*)ioxw; d = g_ioxw16; k = i - CV_E0; }
    else if (i < CV_E2) { s = (const float4*)iohw; d = g_iohw16; k = i - CV_E1; }
    else if (i < CV_E3) { s = (const float4*)fxw;  d = g_fxw16;  k = i - CV_E2; }
    else if (i < CV_E4) { s = (const float4*)fhw;  d = g_fhw16;  k = i - CV_E3; }
    else return;
    float4 v = __ldcs(&s[k]);
    __half2 lo = __float22half2_rn(make_float2(v.x, v.y));
    __half2 hi = __float22half2_rn(make_float2(v.z, v.w));
    uint2 out = { *(uint32_t*)&lo, *(uint32_t*)&hi };
    ((uint2*)d)[k] = out;
}

// ---------------- leaves: nodes 0..383 (single XI slab) ----------------------
__global__ void leaf_k(float* __restrict__ h,
                       const float* __restrict__ ioux_b,
                       const float* __restrict__ iouh_b)
{
    int node = blockIdx.y;
    int j = blockIdx.x * 256 + threadIdx.x;
    const float* xi = g_XI + (size_t)node * TM3;
    float ig = sigm(__ldcs(xi + j) + ioux_b[j] + iouh_b[j]);
    float og = sigm(__ldcs(xi + MEM + j) + ioux_b[MEM + j] + iouh_b[MEM + j]);
    float ug = ftanh(__ldcs(xi + 2 * MEM + j)
                     + ioux_b[2 * MEM + j] + iouh_b[2 * MEM + j]);
    float cv = ig * ug;
    size_t idx = (size_t)node * MEM + j;
    g_c[idx] = cv;
    float hv = og * ftanh(cv);
    h[idx] = hv;
    g_h16[idx] = __float2half(hv);
}

// --- t = (child-sum of h) @ Wrel[rel]^T; register-W, compact groups ----------
__global__ void __launch_bounds__(256) wrel_grp(const float* __restrict__ Wrel,
                                                const float* __restrict__ h,
                                                const int* __restrict__ child_idx,
                                                int lvl)
{
    int gi = blockIdx.y;
    if (gi >= g_ngroups[lvl]) return;
    int r  = g_grp_rel[lvl][gi];
    int s0 = g_grp_startc[lvl][gi];
    int g  = g_grp_startc[lvl][gi + 1] - s0;

    __shared__ float sh[MEM];
    int lane = threadIdx.x & 31, wid = threadIdx.x >> 5;
    int row = blockIdx.x * 8 + wid;
    bool ident = (r == 48);
    float4 w[8];
    if (!ident) {
        const float* W = Wrel + (size_t)r * (MEM * MEM) + (size_t)row * MEM;
        #pragma unroll
        for (int i = 0; i < 8; i++)
            w[i] = __ldcs((const float4*)(W + (i * 32 + lane) * 4));
    }
    for (int j = 0; j < g; j++) {
        int li = g_grp_nodes[lvl][s0 + j];
        int node = li + IBASE;
        const int* ci = child_idx + node * 4;
        int c0 = ci[0], c1 = ci[1], c2 = ci[2], c3 = ci[3];
        {
            int i = threadIdx.x;
            float4 s = make_float4(0.f, 0.f, 0.f, 0.f);
            if (c0 >= 0) { float4 v = ((const float4*)(h + (size_t)c0 * MEM))[i];
                           s.x += v.x; s.y += v.y; s.z += v.z; s.w += v.w; }
            if (c1 >= 0) { float4 v = ((const float4*)(h + (size_t)c1 * MEM))[i];
                           s.x += v.x; s.y += v.y; s.z += v.z; s.w += v.w; }
            if (c2 >= 0) { float4 v = ((const float4*)(h + (size_t)c2 * MEM))[i];
                           s.x += v.x; s.y += v.y; s.z += v.z; s.w += v.w; }
            if (c3 >= 0) { float4 v = ((const float4*)(h + (size_t)c3 * MEM))[i];
                           s.x += v.x; s.y += v.y; s.z += v.z; s.w += v.w; }
            ((float4*)sh)[i] = s;
        }
        __syncthreads();
        float s;
        if (ident) {
            s = sh[row];
        } else {
            s = 0.f;
            #pragma unroll
            for (int i = 0; i < 8; i++) {
                int k4 = (i * 32 + lane) * 4;
                s += w[i].x * sh[k4] + w[i].y * sh[k4 + 1]
                   + w[i].z * sh[k4 + 2] + w[i].w * sh[k4 + 3];
            }
            #pragma unroll
            for (int o = 16; o; o >>= 1) s += __shfl_xor_sync(0xffffffffu, s, o);
        }
        if (lane == 0) g_t16[(size_t)li * MEM + row] = __float2half(s);
        if (j + 1 < g) __syncthreads();
    }
}

// --- fused: fc from children + gates -> h, c ---------------------------------
__global__ void cellfc_k(float* __restrict__ h,
                         const int* __restrict__ child_idx,
                         const float* __restrict__ ioux_b,
                         const float* __restrict__ iouh_b,
                         const float* __restrict__ fx_b,
                         const float* __restrict__ fh_b, int n0)
{
    int node = n0 + blockIdx.y;
    int li = node - IBASE;
    int j = blockIdx.x * 256 + threadIdx.x;
    const int* ci = child_idx + node * 4;

    float xf = 0.f;
    #pragma unroll
    for (int s = 0; s < 4; s++)
        xf += g_XFp[(size_t)s * (NINT * MEM) + (size_t)li * MEM + j];
    float base = xf + fx_b[j] + fh_b[j];

    float fc = 0.f;
    #pragma unroll
    for (int k = 0; k < 4; k++) {
        int c = ci[k];
        if (c >= 0) {
            float fh = g_FHp[(size_t)c * MEM + j]
                     + g_FHp[(size_t)(640 * MEM) + (size_t)c * MEM + j];
            fc += sigm(fh + base) * g_c[(size_t)c * MEM + j];
        }
    }

    float io0 = 0.f, io1 = 0.f, io2 = 0.f;
    #pragma unroll
    for (int s = 0; s < 4; s++) {
        const float* io = g_IOUp + (size_t)s * (128 * TM3) + (size_t)blockIdx.y * TM3;
        io0 += __ldcs(io + j); io1 += __ldcs(io + MEM + j); io2 += __ldcs(io + 2 * MEM + j);
    }
    const float* xi = g_XI + (size_t)node * TM3;

    float ig = sigm(io0 + __ldcs(xi + j) + ioux_b[j] + iouh_b[j]);
    float og = sigm(io1 + __ldcs(xi + MEM + j)
                    + ioux_b[MEM + j] + iouh_b[MEM + j]);
    float ug = ftanh(io2 + __ldcs(xi + 2 * MEM + j)
                     + ioux_b[2 * MEM + j] + iouh_b[2 * MEM + j]);
    float cv = ig * ug + fc;
    size_t idx = (size_t)node * MEM + j;
    g_c[idx] = cv;
    float hv = og * ftanh(cv);
    h[idx] = hv;
    g_h16[idx] = __float2half(hv);
}

// ------------------------------- launcher ------------------------------------
extern "C" void kernel_launch(void* const* d_in, const int* in_sizes, int n_in,
                              void* d_out, int out_size)
{
    const float* x       = (const float*)d_in[0];
    const float* Wrel    = (const float*)d_in[1];
    const float* ioux_w  = (const float*)d_in[2];
    const float* ioux_b  = (const float*)d_in[3];
    const float* iouh_w  = (const float*)d_in[4];
    const float* iouh_b  = (const float*)d_in[5];
    const float* fx_w    = (const float*)d_in[6];
    const float* fx_b    = (const float*)d_in[7];
    const float* fh_w    = (const float*)d_in[8];
    const float* fh_b    = (const float*)d_in[9];
    const int*   child_idx = (const int*)d_in[10];
    const int*   rel_ids   = (const int*)d_in[11];
    float* h = (float*)d_out;

    const int SM128H = 3 * (128 + 128) * SMH * 2;   // 61440 B
    const int SM64H  = 3 * (64 + 128) * SMH * 2;    // 46080 B
    cudaFuncSetAttribute(gemm2h<128>, cudaFuncAttributeMaxDynamicSharedMemorySize, SM128H);
    cudaFuncSetAttribute(gemm2h<64>,  cudaFuncAttributeMaxDynamicSharedMemorySize, SM64H);

    float *p_XI, *p_XFp, *p_FHp, *p_IOUp;
    __half *p_x16, *p_ioxw16, *p_iohw16, *p_fxw16, *p_fhw16, *p_h16, *p_t16;
    cudaGetSymbolAddress((void**)&p_XI,   g_XI);
    cudaGetSymbolAddress((void**)&p_XFp,  g_XFp);
    cudaGetSymbolAddress((void**)&p_FHp,  g_FHp);
    cudaGetSymbolAddress((void**)&p_IOUp, g_IOUp);
    cudaGetSymbolAddress((void**)&p_x16,    g_x16);
    cudaGetSymbolAddress((void**)&p_ioxw16, g_ioxw16);
    cudaGetSymbolAddress((void**)&p_iohw16, g_iohw16);
    cudaGetSymbolAddress((void**)&p_fxw16,  g_fxw16);
    cudaGetSymbolAddress((void**)&p_fhw16,  g_fhw16);
    cudaGetSymbolAddress((void**)&p_h16, g_h16);
    cudaGetSymbolAddress((void**)&p_t16, g_t16);

    // conversion + grouping in one launch
    convh_k<<<CV_BLKS + 1, 256>>>(x, ioux_w, iouh_w, fx_w, fh_w, rel_ids);

    // XI (512x3072, K=1024, z=1) + XF (128x1024, split-K x4), one launch
    GP pXI = { p_x16, p_ioxw16, p_XI, TM3, 1024, NN * TM3, 24, 4, 1 };
    GP pXF = { p_x16 + (size_t)IBASE * KD, p_fxw16, p_XFp, MEM, 256, NINT * MEM, 8, 1, 4 };
    gemm2h<128><<<24 * 4 * 1 + 8 * 1 * 4, 256, SM128H>>>(pXI, pXF);

    leaf_k<<<dim3(4, 384), 256>>>(h, ioux_b, iouh_b);

    // dependency-minimal phases
    const int lvl_n0[NLVL]   = {384, 480, 504, 510, 511};
    const int lvl_cnt[NLVL]  = { 96,  24,   6,   1,   1};
    const int lvl_ngmx[NLVL] = { 48,  24,   6,   1,   1};
    const int lvl_ny[NLVL]   = {  2,   1,   1,   1,   1};   // IOU A rows / 64
    for (int L = 0; L < NLVL; L++) {
        int n0 = lvl_n0[L], cnt = lvl_cnt[L];

        wrel_grp<<<dim3(128, lvl_ngmx[L]), 256>>>(Wrel, h, child_idx, L);

        // IOU(L) (pad M to 64*ny, split-K x4, slab 128 rows) + FH(prev phase)
        GP pIOU = { p_t16 + (size_t)(n0 - IBASE) * MEM, p_iohw16, p_IOUp,
                    TM3, 256, 128 * TM3, 24, lvl_ny[L], 4 };
        GP pFH;
        if (L == 0)          // FH for all 384 leaves (6 x 64 rows)
            pFH = GP{ p_h16, p_fhw16, p_FHp, MEM, 512, 640 * MEM, 8, 6, 2 };
        else {               // FH for previous phase's nodes (pad 64*ny rows)
            int np = lvl_n0[L - 1];
            pFH = GP{ p_h16 + (size_t)np * MEM, p_fhw16, p_FHp + (size_t)np * MEM,
                      MEM, 512, 640 * MEM, 8, lvl_ny[L - 1], 2 };
        }
        int tot = pIOU.nx * pIOU.ny * pIOU.nz + pFH.nx * pFH.ny * pFH.nz;
        gemm2h<64><<<tot, 256, SM64H>>>(pIOU, pFH);

        cellfc_k<<<dim3(4, cnt), 256>>>(h, child_idx, ioux_b, iouh_b, fx_b, fh_b, n0);
    }
}